// round 5
// baseline (speedup 1.0000x reference)
#include <cuda_runtime.h>
#include <cuda_bf16.h>

// MultiScaleEdgeBuilder: B=64 graphs x 256 nodes.
// E = 64 * 256*255 = 4,177,920 ordered intra-graph pairs.
// Output layout (float32, concatenated flattened reference outputs):
//   [0,        2E)  edge_index  [2,E]  (row block then col block)
//   [2E,      18E)  edge_attr   [E,16] zeros
//   [18E,     21E)  rbf         [E,3]  exp(-(d/c)^2), c in {4,8,12}
//
// rbf trick: r = exp(-d2/576) -> {r^36, r^9, r^4}.
// R4: stage pos in SMEM (SoA, XOR bank swizzle) to kill the 12-line-per-LDG
// col gather that kept l1tex at 75% and throttled the store stream.

namespace {
constexpr int NPER   = 256;
constexpr int NGRAPH = 64;
constexpr int NTOT   = NGRAPH * NPER;       // 16384 nodes
constexpr int PAIRS  = NPER * (NPER - 1);   // 65280  (divisible by 4)
constexpr int E      = NGRAPH * PAIRS;      // 4177920
constexpr int Q      = E / 4;               // 1044480 threads, 4 edges each
constexpr int NTHR   = 256;
constexpr int NBLK   = Q / NTHR;            // 4080 exactly
constexpr int SNODES = 2 * NPER;            // a block's 1024 edges touch <=2 graphs
}

__device__ __forceinline__ int swz(int j) { return j ^ ((j >> 5) & 3); }

__global__ __launch_bounds__(NTHR) void edge_builder_kernel(
    const float* __restrict__ pos, float* __restrict__ out)
{
    __shared__ float sx[SNODES], sy[SNODES], sz[SNODES];

    const int tid = threadIdx.x;
    const int blk = blockIdx.x;
    const int idx = blk * NTHR + tid;                 // [0, Q)
    const int e0  = idx * 4;

    // ---- Stage pos for the graphs this block touches (<=512 nodes) ----
    const int eblk0  = blk * (NTHR * 4);
    const int g_lo   = eblk0 / PAIRS;
    const int nbase  = g_lo * NPER;
    const int navail = min(SNODES, NTOT - nbase);
    const int favail = 3 * navail;
    const float* __restrict__ psrc = pos + (size_t)nbase * 3;
#pragma unroll 2
    for (int i = tid; i < favail; i += NTHR) {
        const float v = __ldg(&psrc[i]);
        const int node = i / 3;                       // const-div -> mul/shift
        const int c    = i - node * 3;
        const int a    = swz(node);
        if (c == 0)      sx[a] = v;
        else if (c == 1) sy[a] = v;
        else             sz[a] = v;
    }
    __syncthreads();

    // ---- 4 edges per thread (all in one graph: PAIRS % 4 == 0) ----
    const int g     = e0 / PAIRS;
    const int p0    = e0 - g * PAIRS;
    const int gbase = g * NPER;                       // global node base
    const int lbase = (g - g_lo) * NPER;              // smem node base (0 or 256)

    float rowv[4], colv[4], rb[12];

#pragma unroll
    for (int k = 0; k < 4; ++k) {
        const int p  = p0 + k;
        const int ia = p / 255;
        const int r  = p - ia * 255;
        const int ib = r + (r >= ia ? 1 : 0);
        rowv[k] = (float)(gbase + ia);
        colv[k] = (float)(gbase + ib);

        const int aa = swz(lbase + ia);               // ~broadcast across lanes
        const int ab = swz(lbase + ib);               // stride-4 -> conflict-free via swz

        const float dx = sx[aa] - sx[ab];
        const float dy = sy[aa] - sy[ab];
        const float dz = sz[aa] - sz[ab];
        const float d2 = dx * dx + dy * dy + dz * dz;

        const float rbse = __expf(-d2 * (1.0f / 576.0f));
        const float r2  = rbse * rbse;
        const float r4  = r2 * r2;
        const float r8  = r4 * r4;
        const float r9  = r8 * rbse;
        const float r16 = r8 * r8;
        const float r32 = r16 * r16;
        const float r36 = r32 * r4;
        rb[3 * k + 0] = r36;   // exp(-d2/16)   cutoff 4
        rb[3 * k + 1] = r9;    // exp(-d2/64)   cutoff 8
        rb[3 * k + 2] = r4;    // exp(-d2/144)  cutoff 12
    }

    // ---- Stores: unchanged, all 128-bit, line-complete ----
    float4* __restrict__ orow = reinterpret_cast<float4*>(out);
    float4* __restrict__ ocol = reinterpret_cast<float4*>(out + (size_t)E);
    orow[idx] = make_float4(rowv[0], rowv[1], rowv[2], rowv[3]);
    ocol[idx] = make_float4(colv[0], colv[1], colv[2], colv[3]);

    float4* __restrict__ oz = reinterpret_cast<float4*>(out + 2 * (size_t)E);
    const float4 z4 = make_float4(0.f, 0.f, 0.f, 0.f);
#pragma unroll
    for (int k = 0; k < 16; ++k)
        oz[(size_t)k * Q + idx] = z4;

    float4* __restrict__ orbf = reinterpret_cast<float4*>(out + 18 * (size_t)E);
    orbf[3 * (size_t)idx + 0] = make_float4(rb[0], rb[1], rb[2],  rb[3]);
    orbf[3 * (size_t)idx + 1] = make_float4(rb[4], rb[5], rb[6],  rb[7]);
    orbf[3 * (size_t)idx + 2] = make_float4(rb[8], rb[9], rb[10], rb[11]);
}

extern "C" void kernel_launch(void* const* d_in, const int* in_sizes, int n_in,
                              void* d_out, int out_size)
{
    const float* pos = (const float*)d_in[0];   // [N,3] float32
    float* out = (float*)d_out;                 // 21*E float32
    edge_builder_kernel<<<NBLK, NTHR>>>(pos, out);
}

// round 6
// speedup vs baseline: 1.0467x; 1.0467x over previous
#include <cuda_runtime.h>
#include <cuda_bf16.h>

// MultiScaleEdgeBuilder: B=64 graphs x 256 nodes.
// E = 64 * 256*255 = 4,177,920 ordered intra-graph pairs.
// Output layout (float32, concatenated flattened reference outputs):
//   [0,        2E)  edge_index  [2,E]  (row block then col block)
//   [2E,      18E)  edge_attr   [E,16] zeros
//   [18E,     21E)  rbf         [E,3]  exp(-(d/c)^2), c in {4,8,12}
//
// rbf trick: r = exp(-d2/576) -> {r^36, r^9, r^4}: 1 MUFU + 7 FMUL per edge.
// R5: revert R4's SMEM staging (l1tex counts LDS too -> no win, issue 2x).
//     All 21 stores/thread now STG.128.CS (evict-first): the kernel streams
//     351MB through a 126MB L2; evict-normal let dirty lines pile up and
//     drain reactively (profiled 6.6TB/s apparent vs 5.47TB/s HBM => dirty
//     tail at retire). Streaming stores start writeback eagerly.

namespace {
constexpr int NPER   = 256;
constexpr int NGRAPH = 64;
constexpr int PAIRS  = NPER * (NPER - 1);   // 65280  (divisible by 4)
constexpr int E      = NGRAPH * PAIRS;      // 4177920
constexpr int Q      = E / 4;               // 1044480 threads, 4 edges each
constexpr int NTHR   = 256;
constexpr int NBLK   = Q / NTHR;            // 4080 exactly
}

__global__ __launch_bounds__(NTHR) void edge_builder_kernel(
    const float* __restrict__ pos, float* __restrict__ out)
{
    const int idx = blockIdx.x * NTHR + threadIdx.x;   // [0, Q)
    const int e0  = idx * 4;

    // All 4 edges of this thread live in the same graph (PAIRS % 4 == 0).
    const int g    = e0 / PAIRS;
    const int p0   = e0 - g * PAIRS;
    const int base = g * NPER;

    float rowv[4], colv[4], rb[12];

#pragma unroll
    for (int k = 0; k < 4; ++k) {
        const int p  = p0 + k;
        const int ia = p / 255;           // constant division -> mul/shift
        const int r  = p - ia * 255;
        const int ib = r + (r >= ia ? 1 : 0);
        const int rowi = base + ia;
        const int coli = base + ib;
        rowv[k] = (float)rowi;
        colv[k] = (float)coli;

        const float dx = __ldg(&pos[3 * rowi + 0]) - __ldg(&pos[3 * coli + 0]);
        const float dy = __ldg(&pos[3 * rowi + 1]) - __ldg(&pos[3 * coli + 1]);
        const float dz = __ldg(&pos[3 * rowi + 2]) - __ldg(&pos[3 * coli + 2]);
        const float d2 = dx * dx + dy * dy + dz * dz;

        const float rbse = __expf(-d2 * (1.0f / 576.0f));
        const float r2  = rbse * rbse;
        const float r4  = r2 * r2;
        const float r8  = r4 * r4;
        const float r9  = r8 * rbse;
        const float r16 = r8 * r8;
        const float r32 = r16 * r16;
        const float r36 = r32 * r4;
        rb[3 * k + 0] = r36;   // exp(-d2/16)   cutoff 4
        rb[3 * k + 1] = r9;    // exp(-d2/64)   cutoff 8
        rb[3 * k + 2] = r4;    // exp(-d2/144)  cutoff 12
    }

    // ---- Stores: all 128-bit, line-complete, cache-streaming (evict-first) ----
    float4* __restrict__ orow = reinterpret_cast<float4*>(out);
    float4* __restrict__ ocol = reinterpret_cast<float4*>(out + (size_t)E);
    __stcs(&orow[idx], make_float4(rowv[0], rowv[1], rowv[2], rowv[3]));
    __stcs(&ocol[idx], make_float4(colv[0], colv[1], colv[2], colv[3]));

    // edge_attr zeros: 16E floats = 4E float4, remapped so each of the 16
    // stores per thread is warp-coalesced (stride Q between k's).
    float4* __restrict__ oz = reinterpret_cast<float4*>(out + 2 * (size_t)E);
    const float4 z4 = make_float4(0.f, 0.f, 0.f, 0.f);
#pragma unroll
    for (int k = 0; k < 16; ++k)
        __stcs(&oz[(size_t)k * Q + idx], z4);

    // rbf [E,3]: 12 contiguous floats per thread = 3 float4
    float4* __restrict__ orbf = reinterpret_cast<float4*>(out + 18 * (size_t)E);
    __stcs(&orbf[3 * (size_t)idx + 0], make_float4(rb[0], rb[1], rb[2],  rb[3]));
    __stcs(&orbf[3 * (size_t)idx + 1], make_float4(rb[4], rb[5], rb[6],  rb[7]));
    __stcs(&orbf[3 * (size_t)idx + 2], make_float4(rb[8], rb[9], rb[10], rb[11]));
}

extern "C" void kernel_launch(void* const* d_in, const int* in_sizes, int n_in,
                              void* d_out, int out_size)
{
    const float* pos = (const float*)d_in[0];   // [N,3] float32
    float* out = (float*)d_out;                 // 21*E float32
    edge_builder_kernel<<<NBLK, NTHR>>>(pos, out);
}